// round 12
// baseline (speedup 1.0000x reference)
#include <cuda_runtime.h>
#include <cstdint>

// Binarized NAND conv-net, fully fused, one warp per 32 images.
// bit=1 <=> value=+1. Conv over N taps: y = N - 2*popcount(xor);
// NAND output bit = (mismatch >= N/2).
// 16-ch activations: one halfword per position, 2 positions per u32.
// 2x2x16 window => one u64 => one popcll per filter.
// L0 (1ch, 4 taps, 16 filters) is a 16-entry LUT: nibble -> halfword.

#define HG(arr, y, xx) ((arr[(y)][(xx) >> 1] >> (((xx) & 1) * 16)) & 0xFFFFu)

// All-16-filter NAND conv on one 64-bit window. Branch-free bit build:
// bit_f = (popcll(T^W_f) >= 32) computed as sign((31 - sum)) ; accumulate
// h = (h << 1) | bit walking f = 15..0 so bit f lands at position f.
__device__ __forceinline__ unsigned filt16(const unsigned long long (&W)[16],
                                           unsigned long long T) {
    unsigned h = 0u;
#pragma unroll
    for (int f = 15; f >= 0; --f) {
        const int s = __popcll(T ^ W[f]);
        h = (h << 1) | ((unsigned)(31 - s) >> 31);   // 1 iff s >= 32
    }
    return h;
}

__global__ __launch_bounds__(32) void nand_mnist_kernel(
    const float* __restrict__ x,
    const float* __restrict__ w0,
    const float* __restrict__ w1,
    const float* __restrict__ w2,
    const float* __restrict__ w3,
    const float* __restrict__ w4,
    const float* __restrict__ w5,
    float* __restrict__ out,
    int B)
{
    __shared__ unsigned s_wb0[16];
    __shared__ unsigned s_lut0[16];            // nibble -> halfword of 16 L0 outputs
    __shared__ unsigned long long s_W[4][16];  // L1..L4 64-bit weight masks
    __shared__ unsigned s_W5[10];              // L5 16-bit weight masks

    const int t = threadIdx.x;                 // 0..31

    // ---- bit-pack weights into shared ----
    if (t < 16) {
        unsigned wb = 0u;
#pragma unroll
        for (int k = 0; k < 4; ++k)            // bit k = ky*2+kx
            if (w0[t * 4 + k] > 0.0f) wb |= 1u << k;
        s_wb0[t] = wb;
    }
    if (t < 10) {
        unsigned m = 0u;
#pragma unroll
        for (int ci = 0; ci < 16; ++ci)
            if (w5[t * 16 + ci] > 0.0f) m |= 1u << ci;
        s_W5[t] = m;
    }
#pragma unroll
    for (int idx = t; idx < 64; idx += 32) {   // 64 filter masks for w1..w4
        const int L = idx >> 4;
        const int f = idx & 15;
        const float* w = (L == 0) ? w1 : (L == 1) ? w2 : (L == 2) ? w3 : w4;
        unsigned long long m = 0ull;
#pragma unroll
        for (int ci = 0; ci < 16; ++ci)
#pragma unroll
            for (int ky = 0; ky < 2; ++ky)
#pragma unroll
                for (int kx = 0; kx < 2; ++kx)
                    if (w[((f * 16 + ci) * 2 + ky) * 2 + kx] > 0.0f)
                        m |= 1ull << (ky * 32 + kx * 16 + ci);
        s_W[L][f] = m;
    }
    __syncthreads();
    if (t < 16) {                              // t = input nibble value
        unsigned h = 0u;
#pragma unroll
        for (int f = 0; f < 16; ++f)
            if (__popc((unsigned)t ^ s_wb0[f]) >= 2) h |= 1u << f;  // m>=2 -> +1
        s_lut0[t] = h;
    }
    __syncthreads();

    const int lane = t;
    const int imgBase = (int)blockIdx.x * 32;
    const int myImg = imgBase + lane;

    // ---- warp-cooperative binarize: coalesced streaming loads + ballot ----
    // lane `img` ends up holding image (imgBase+img) as 25 sign words.
    unsigned iw[25];
    {
        const float* pb = x + (size_t)imgBase * 784;
        if (imgBase + 32 <= B) {               // full warp: constant trip count
#pragma unroll 2
            for (int img = 0; img < 32; ++img) {
                const float* p = pb + img * 784;
                float v[25];
#pragma unroll
                for (int j = 0; j < 25; ++j) {
                    const int e = j * 32 + lane;
                    v[j] = (e < 784) ? __ldcs(p + e) : -1.0f;
                }
#pragma unroll
                for (int j = 0; j < 25; ++j) {
                    const unsigned b = __ballot_sync(0xFFFFFFFFu, v[j] > 0.0f);
                    if (lane == img) iw[j] = b;
                }
            }
        } else {
            for (int img = 0; img < 32; ++img) {
                if (imgBase + img >= B) break; // warp-uniform
                const float* p = pb + img * 784;
                float v[25];
#pragma unroll
                for (int j = 0; j < 25; ++j) {
                    const int e = j * 32 + lane;
                    v[j] = (e < 784) ? __ldcs(p + e) : -1.0f;
                }
#pragma unroll
                for (int j = 0; j < 25; ++j) {
                    const unsigned b = __ballot_sync(0xFFFFFFFFu, v[j] > 0.0f);
                    if (lane == img) iw[j] = b;
                }
            }
        }
    }

    if (myImg >= B) return;                    // no further __syncthreads below

    unsigned long long W[16];

    // ---- L0 (LUT) + L1 (k=2, s=2) fused: 28x28 bits -> 7x7 halfwords ----
    unsigned a1[7][4];
#pragma unroll
    for (int i = 0; i < 7; ++i)
#pragma unroll
        for (int j = 0; j < 4; ++j) a1[i][j] = 0u;

#pragma unroll
    for (int f = 0; f < 16; ++f) W[f] = s_W[0][f];

#pragma unroll
    for (int oy = 0; oy < 7; ++oy) {
        const int e0 = 28 * (4 * oy + 0);
        const int e1 = 28 * (4 * oy + 1);
        const int e2 = 28 * (4 * oy + 2);
        const int e3 = 28 * (4 * oy + 3);
        const unsigned r0 = __funnelshift_r(iw[e0 >> 5], iw[(e0 >> 5) + 1], e0 & 31);
        const unsigned r1 = __funnelshift_r(iw[e1 >> 5], iw[(e1 >> 5) + 1], e1 & 31);
        const unsigned r2 = __funnelshift_r(iw[e2 >> 5], iw[(e2 >> 5) + 1], e2 & 31);
        const unsigned r3 = __funnelshift_r(iw[e3 >> 5], iw[(e3 >> 5) + 1], e3 & 31);
#pragma unroll
        for (int ox = 0; ox < 7; ++ox) {
            const int c = 4 * ox;
            const unsigned nib00 = ((r0 >> c) & 3u) | (((r1 >> c) & 3u) << 2);
            const unsigned nib01 = ((r0 >> (c + 2)) & 3u) | (((r1 >> (c + 2)) & 3u) << 2);
            const unsigned nib10 = ((r2 >> c) & 3u) | (((r3 >> c) & 3u) << 2);
            const unsigned nib11 = ((r2 >> (c + 2)) & 3u) | (((r3 >> (c + 2)) & 3u) << 2);
            const unsigned lo = s_lut0[nib00] | (s_lut0[nib01] << 16);
            const unsigned hi = s_lut0[nib10] | (s_lut0[nib11] << 16);
            const unsigned long long T = (unsigned long long)lo |
                                         ((unsigned long long)hi << 32);
            const unsigned h = filt16(W, T);
            a1[oy][ox >> 1] |= h << ((ox & 1) * 16);
        }
    }

    // ---- L2 (k=2, s=1): 7x7 -> 6x6 ----
#pragma unroll
    for (int f = 0; f < 16; ++f) W[f] = s_W[1][f];
    unsigned a2[6][3];
#pragma unroll
    for (int i = 0; i < 6; ++i)
#pragma unroll
        for (int j = 0; j < 3; ++j) a2[i][j] = 0u;

#pragma unroll
    for (int oy = 0; oy < 6; ++oy)
#pragma unroll
        for (int ox = 0; ox < 6; ++ox) {
            const unsigned lo = HG(a1, oy, ox)     | (HG(a1, oy, ox + 1) << 16);
            const unsigned hi = HG(a1, oy + 1, ox) | (HG(a1, oy + 1, ox + 1) << 16);
            const unsigned long long T = (unsigned long long)lo |
                                         ((unsigned long long)hi << 32);
            const unsigned h = filt16(W, T);
            a2[oy][ox >> 1] |= h << ((ox & 1) * 16);
        }

    // ---- L3 (k=2, s=2): 6x6 -> 3x3 ----
#pragma unroll
    for (int f = 0; f < 16; ++f) W[f] = s_W[2][f];
    unsigned a3[3][2];
#pragma unroll
    for (int i = 0; i < 3; ++i)
#pragma unroll
        for (int j = 0; j < 2; ++j) a3[i][j] = 0u;

#pragma unroll
    for (int oy = 0; oy < 3; ++oy)
#pragma unroll
        for (int ox = 0; ox < 3; ++ox) {
            const int iy = 2 * oy, ix = 2 * ox;
            const unsigned lo = HG(a2, iy, ix)     | (HG(a2, iy, ix + 1) << 16);
            const unsigned hi = HG(a2, iy + 1, ix) | (HG(a2, iy + 1, ix + 1) << 16);
            const unsigned long long T = (unsigned long long)lo |
                                         ((unsigned long long)hi << 32);
            const unsigned h = filt16(W, T);
            a3[oy][ox >> 1] |= h << ((ox & 1) * 16);
        }

    // ---- L4 (k=2, s=2): 3x3 -> 1x1 ----
#pragma unroll
    for (int f = 0; f < 16; ++f) W[f] = s_W[3][f];
    unsigned h4;
    {
        const unsigned lo = HG(a3, 0, 0) | (HG(a3, 0, 1) << 16);
        const unsigned hi = HG(a3, 1, 0) | (HG(a3, 1, 1) << 16);
        const unsigned long long T = (unsigned long long)lo |
                                     ((unsigned long long)hi << 32);
        h4 = filt16(W, T);
    }

    // ---- L5 (k=1): 16 -> 10, vectorized +/-1.0f stores ----
    float2* o2 = (float2*)(out + (size_t)myImg * 10);   // 8B-aligned (40B stride)
#pragma unroll
    for (int f = 0; f < 10; f += 2) {
        float2 v;
        v.x = (__popc(h4 ^ s_W5[f])     >= 8) ? 1.0f : -1.0f;
        v.y = (__popc(h4 ^ s_W5[f + 1]) >= 8) ? 1.0f : -1.0f;
        o2[f >> 1] = v;
    }
}

extern "C" void kernel_launch(void* const* d_in, const int* in_sizes, int n_in,
                              void* d_out, int out_size) {
    const float* x  = (const float*)d_in[0];
    const float* w0 = (const float*)d_in[1];
    const float* w1 = (const float*)d_in[2];
    const float* w2 = (const float*)d_in[3];
    const float* w3 = (const float*)d_in[4];
    const float* w4 = (const float*)d_in[5];
    const float* w5 = (const float*)d_in[6];
    float* out = (float*)d_out;

    const int B = in_sizes[0] / 784;
    const int blocks = (B + 31) / 32;          // one warp (32 images) per block
    nand_mnist_kernel<<<blocks, 32>>>(x, w0, w1, w2, w3, w4, w5, out, B);
}